// round 1
// baseline (speedup 1.0000x reference)
#include <cuda_runtime.h>

#define NPTS  32768
#define BATCH 8
#define CH    128
#define RES   32
#define R3    32768   // 32^3

// Scratch (device globals: no allocation allowed)
__device__ float g_grid[(size_t)BATCH * R3 * CH];   // [b][voxel][c]  (x2 sums)
__device__ float g_cnt[BATCH * R3];                 // [b][voxel]
__device__ float g_stats[2][BATCH][4];              // [tensor][b][{mx,my,mz,inv2m}]

// ---------------------------------------------------------------------------
// Zero the scatter grid + counts (needed every replay: graph re-executes)
// ---------------------------------------------------------------------------
__global__ void zero_kernel() {
    const size_t gtotal = (size_t)BATCH * R3 * CH / 4;
    float4* p = (float4*)g_grid;
    size_t stride = (size_t)gridDim.x * blockDim.x;
    for (size_t i = (size_t)blockIdx.x * blockDim.x + threadIdx.x; i < gtotal; i += stride)
        p[i] = make_float4(0.f, 0.f, 0.f, 0.f);
    const size_t ctotal = (size_t)BATCH * R3 / 4;
    float4* q = (float4*)g_cnt;
    for (size_t i = (size_t)blockIdx.x * blockDim.x + threadIdx.x; i < ctotal; i += stride)
        q[i] = make_float4(0.f, 0.f, 0.f, 0.f);
}

// ---------------------------------------------------------------------------
// Per-batch coordinate mean (both coord tensors). 16 blocks, 256 threads.
// ---------------------------------------------------------------------------
__global__ void mean_kernel(const float* __restrict__ c1, const float* __restrict__ c2) {
    int t = blockIdx.x >> 3;
    int b = blockIdx.x & 7;
    const float* c = (t == 0 ? c1 : c2) + (size_t)b * 3 * NPTS;

    float s0 = 0.f, s1 = 0.f, s2 = 0.f;
    for (int n = threadIdx.x; n < NPTS; n += blockDim.x) {
        s0 += c[n];
        s1 += c[NPTS + n];
        s2 += c[2 * NPTS + n];
    }
    #pragma unroll
    for (int off = 16; off; off >>= 1) {
        s0 += __shfl_down_sync(0xffffffffu, s0, off);
        s1 += __shfl_down_sync(0xffffffffu, s1, off);
        s2 += __shfl_down_sync(0xffffffffu, s2, off);
    }
    __shared__ float red[3][8];
    int lane = threadIdx.x & 31, w = threadIdx.x >> 5;
    if (lane == 0) { red[0][w] = s0; red[1][w] = s1; red[2][w] = s2; }
    __syncthreads();
    if (threadIdx.x == 0) {
        float m0 = 0.f, m1 = 0.f, m2 = 0.f;
        #pragma unroll
        for (int i = 0; i < 8; i++) { m0 += red[0][i]; m1 += red[1][i]; m2 += red[2][i]; }
        g_stats[t][b][0] = m0 * (1.0f / NPTS);
        g_stats[t][b][1] = m1 * (1.0f / NPTS);
        g_stats[t][b][2] = m2 * (1.0f / NPTS);
    }
}

// ---------------------------------------------------------------------------
// Per-batch max ||coord - mean||  ->  store 1/(2*max)
// ---------------------------------------------------------------------------
__global__ void max_kernel(const float* __restrict__ c1, const float* __restrict__ c2) {
    int t = blockIdx.x >> 3;
    int b = blockIdx.x & 7;
    const float* c = (t == 0 ? c1 : c2) + (size_t)b * 3 * NPTS;
    float mx = g_stats[t][b][0], my = g_stats[t][b][1], mz = g_stats[t][b][2];

    float best = 0.f;
    for (int n = threadIdx.x; n < NPTS; n += blockDim.x) {
        float x = c[n] - mx;
        float y = c[NPTS + n] - my;
        float z = c[2 * NPTS + n] - mz;
        float n2 = x * x + y * y + z * z;
        best = fmaxf(best, n2);
    }
    #pragma unroll
    for (int off = 16; off; off >>= 1)
        best = fmaxf(best, __shfl_down_sync(0xffffffffu, best, off));
    __shared__ float red[8];
    int lane = threadIdx.x & 31, w = threadIdx.x >> 5;
    if (lane == 0) red[w] = best;
    __syncthreads();
    if (threadIdx.x == 0) {
        float m = 0.f;
        #pragma unroll
        for (int i = 0; i < 8; i++) m = fmaxf(m, red[i]);
        g_stats[t][b][3] = 0.5f / sqrtf(m);   // 1/(2*max_norm)
    }
}

// ---------------------------------------------------------------------------
// Scatter x2 features into grid (avg_voxelize numerator) + counts.
// 32 points/block, 256 threads. smem transpose keeps all gmem ops coalesced.
// ---------------------------------------------------------------------------
__global__ void scatter_kernel(const float* __restrict__ x2f, const float* __restrict__ x2c) {
    int b    = blockIdx.x >> 10;       // 1024 tiles per batch
    int tile = blockIdx.x & 1023;
    int n0   = tile * 32;
    int tx = threadIdx.x, warp = tx >> 5, lane = tx & 31;

    __shared__ float sm[CH][33];
    __shared__ int   sidx[32];

    if (tx < 32) {
        int n = n0 + tx;
        const float* c = x2c + (size_t)b * 3 * NPTS;
        float inv = g_stats[1][b][3];
        float fx = ((c[n]            - g_stats[1][b][0]) * inv + 0.5f) * (float)RES;
        float fy = ((c[NPTS + n]     - g_stats[1][b][1]) * inv + 0.5f) * (float)RES;
        float fz = ((c[2 * NPTS + n] - g_stats[1][b][2]) * inv + 0.5f) * (float)RES;
        int vx = (int)rintf(fminf(fmaxf(fx, 0.f), (float)(RES - 1)));
        int vy = (int)rintf(fminf(fmaxf(fy, 0.f), (float)(RES - 1)));
        int vz = (int)rintf(fminf(fmaxf(fz, 0.f), (float)(RES - 1)));
        int v = (vx * RES + vy) * RES + vz;
        sidx[tx] = v;
        atomicAdd(&g_cnt[b * R3 + v], 1.0f);
    }
    // transpose-load features: warp reads 32 consecutive points for one channel
    const float* fbase = x2f + (size_t)b * CH * NPTS + n0;
    #pragma unroll
    for (int c = warp; c < CH; c += 8)
        sm[c][lane] = fbase[(size_t)c * NPTS + lane];
    __syncthreads();

    // per-point coalesced atomics: warp covers 128 channels in 4 strides
    for (int p = warp; p < 32; p += 8) {
        float* base = g_grid + ((size_t)b * R3 + sidx[p]) * CH;
        #pragma unroll
        for (int k = 0; k < 4; k++)
            atomicAdd(&base[lane + 32 * k], sm[lane + 32 * k][p]);
    }
}

// ---------------------------------------------------------------------------
// Trilinear devoxelize (nc from x1 coords, grid from x2) + concat + x1 copy.
// Normalization folded into per-corner weight: w / max(cnt,1).
// ---------------------------------------------------------------------------
__global__ void devox_kernel(const float* __restrict__ x1f, const float* __restrict__ x1c,
                             float* __restrict__ out) {
    int b    = blockIdx.x >> 10;
    int tile = blockIdx.x & 1023;
    int n0   = tile * 32;
    int tx = threadIdx.x, warp = tx >> 5, lane = tx & 31;

    __shared__ float sm[CH][33];
    __shared__ int   sidx[32][8];
    __shared__ float sw[32][8];

    if (tx < 32) {
        int n = n0 + tx;
        const float* c = x1c + (size_t)b * 3 * NPTS;
        float inv = g_stats[0][b][3];
        float nc[3];
        nc[0] = fminf(fmaxf(((c[n]            - g_stats[0][b][0]) * inv + 0.5f) * (float)RES, 0.f), (float)(RES - 1));
        nc[1] = fminf(fmaxf(((c[NPTS + n]     - g_stats[0][b][1]) * inv + 0.5f) * (float)RES, 0.f), (float)(RES - 1));
        nc[2] = fminf(fmaxf(((c[2 * NPTS + n] - g_stats[0][b][2]) * inv + 0.5f) * (float)RES, 0.f), (float)(RES - 1));
        int lo[3], hi[3];
        float d[3];
        #pragma unroll
        for (int i = 0; i < 3; i++) {
            float f = floorf(nc[i]);
            lo[i] = (int)f;
            d[i]  = nc[i] - f;
            hi[i] = min(lo[i] + 1, RES - 1);
        }
        const float* cnt = g_cnt + b * R3;
        #pragma unroll
        for (int k = 0; k < 8; k++) {
            int xi = (k & 4) ? hi[0] : lo[0];
            int yi = (k & 2) ? hi[1] : lo[1];
            int zi = (k & 1) ? hi[2] : lo[2];
            float w = ((k & 4) ? d[0] : 1.f - d[0]) *
                      ((k & 2) ? d[1] : 1.f - d[1]) *
                      ((k & 1) ? d[2] : 1.f - d[2]);
            int v = (xi * RES + yi) * RES + zi;
            sidx[tx][k] = v;
            sw[tx][k]   = w / fmaxf(cnt[v], 1.0f);
        }
    }
    __syncthreads();

    // gather-accumulate: warp handles a point, lanes cover channels (coalesced)
    const float* gbase = g_grid + (size_t)b * R3 * CH;
    for (int p = warp; p < 32; p += 8) {
        #pragma unroll
        for (int k = 0; k < 4; k++) {
            int ch = lane + 32 * k;
            float acc = 0.f;
            #pragma unroll
            for (int c8 = 0; c8 < 8; c8++)
                acc += sw[p][c8] * gbase[(size_t)sidx[p][c8] * CH + ch];
            sm[ch][p] = acc;
        }
    }
    __syncthreads();

    // coalesced write-out: devox half + x1 copy half
    const float* x1base = x1f + (size_t)b * CH * NPTS + n0;
    float* obase = out + (size_t)b * 2 * CH * NPTS + n0;
    #pragma unroll
    for (int c = warp; c < CH; c += 8) {
        obase[(size_t)c * NPTS + lane]        = x1base[(size_t)c * NPTS + lane];
        obase[(size_t)(CH + c) * NPTS + lane] = sm[c][lane];
    }
}

// ---------------------------------------------------------------------------
extern "C" void kernel_launch(void* const* d_in, const int* in_sizes, int n_in,
                              void* d_out, int out_size) {
    const float* x1f = (const float*)d_in[0];
    const float* x2f = (const float*)d_in[1];
    const float* x1c = (const float*)d_in[2];
    const float* x2c = (const float*)d_in[3];
    float* out = (float*)d_out;

    zero_kernel<<<2048, 256>>>();
    mean_kernel<<<16, 256>>>(x1c, x2c);
    max_kernel<<<16, 256>>>(x1c, x2c);
    scatter_kernel<<<BATCH * (NPTS / 32), 256>>>(x2f, x2c);
    devox_kernel<<<BATCH * (NPTS / 32), 256>>>(x1f, x1c, out);
}

// round 2
// speedup vs baseline: 1.3859x; 1.3859x over previous
#include <cuda_runtime.h>
#include <cuda_fp16.h>

#define NPTS  32768
#define BATCH 8
#define CH    128
#define RES   32
#define R3    32768   // 32^3

// Scratch (device globals: no allocation allowed)
__device__ float  g_grid [(size_t)BATCH * R3 * CH];   // fp32 scatter sums [b][v][c]
__device__ __half g_gridh[(size_t)BATCH * R3 * CH];   // fp16 averaged grid
__device__ float  g_cnt  [BATCH * R3];
__device__ float  g_sum  [2][BATCH][3];               // mean partials (atomicAdd)
__device__ int    g_max  [2][BATCH];                  // max ||c-mean||^2 as int bits

// ---------------------------------------------------------------------------
// Zero fp32 grid + counts + stat accumulators (graph replays -> every launch)
// ---------------------------------------------------------------------------
__global__ void zero_kernel() {
    const size_t gtotal = (size_t)BATCH * R3 * CH / 4;
    float4* p = (float4*)g_grid;
    size_t stride = (size_t)gridDim.x * blockDim.x;
    for (size_t i = (size_t)blockIdx.x * blockDim.x + threadIdx.x; i < gtotal; i += stride)
        p[i] = make_float4(0.f, 0.f, 0.f, 0.f);
    const size_t ctotal = (size_t)BATCH * R3 / 4;
    float4* q = (float4*)g_cnt;
    for (size_t i = (size_t)blockIdx.x * blockDim.x + threadIdx.x; i < ctotal; i += stride)
        q[i] = make_float4(0.f, 0.f, 0.f, 0.f);
    if (blockIdx.x == 0 && threadIdx.x < 64) {
        if (threadIdx.x < 48) ((float*)g_sum)[threadIdx.x] = 0.f;
        else                  ((int*)g_max)[threadIdx.x - 48] = 0;
    }
}

// ---------------------------------------------------------------------------
// Mean partials: 128 blocks (2 tensors x 8 batches x 8 chunks)
// ---------------------------------------------------------------------------
__global__ void mean_kernel(const float* __restrict__ c1, const float* __restrict__ c2) {
    int id = blockIdx.x;
    int t = id >> 6, b = (id >> 3) & 7, s = id & 7;
    const float* c = (t ? c2 : c1) + (size_t)b * 3 * NPTS + s * 4096;

    float s0 = 0.f, s1 = 0.f, s2 = 0.f;
    for (int n = threadIdx.x; n < 4096; n += 256) {
        s0 += c[n]; s1 += c[NPTS + n]; s2 += c[2 * NPTS + n];
    }
    #pragma unroll
    for (int off = 16; off; off >>= 1) {
        s0 += __shfl_down_sync(0xffffffffu, s0, off);
        s1 += __shfl_down_sync(0xffffffffu, s1, off);
        s2 += __shfl_down_sync(0xffffffffu, s2, off);
    }
    __shared__ float red[3][8];
    int lane = threadIdx.x & 31, w = threadIdx.x >> 5;
    if (lane == 0) { red[0][w] = s0; red[1][w] = s1; red[2][w] = s2; }
    __syncthreads();
    if (threadIdx.x == 0) {
        float m0 = 0.f, m1 = 0.f, m2 = 0.f;
        #pragma unroll
        for (int i = 0; i < 8; i++) { m0 += red[0][i]; m1 += red[1][i]; m2 += red[2][i]; }
        atomicAdd(&g_sum[t][b][0], m0);
        atomicAdd(&g_sum[t][b][1], m1);
        atomicAdd(&g_sum[t][b][2], m2);
    }
}

// ---------------------------------------------------------------------------
// Max ||c - mean||^2 partials (int-bit atomicMax, values >= 0)
// ---------------------------------------------------------------------------
__global__ void max_kernel(const float* __restrict__ c1, const float* __restrict__ c2) {
    int id = blockIdx.x;
    int t = id >> 6, b = (id >> 3) & 7, s = id & 7;
    const float* c = (t ? c2 : c1) + (size_t)b * 3 * NPTS + s * 4096;
    float mx = g_sum[t][b][0] * (1.0f / NPTS);
    float my = g_sum[t][b][1] * (1.0f / NPTS);
    float mz = g_sum[t][b][2] * (1.0f / NPTS);

    float best = 0.f;
    for (int n = threadIdx.x; n < 4096; n += 256) {
        float x = c[n] - mx, y = c[NPTS + n] - my, z = c[2 * NPTS + n] - mz;
        best = fmaxf(best, x * x + y * y + z * z);
    }
    #pragma unroll
    for (int off = 16; off; off >>= 1)
        best = fmaxf(best, __shfl_down_sync(0xffffffffu, best, off));
    __shared__ float red[8];
    int lane = threadIdx.x & 31, w = threadIdx.x >> 5;
    if (lane == 0) red[w] = best;
    __syncthreads();
    if (threadIdx.x == 0) {
        float m = 0.f;
        #pragma unroll
        for (int i = 0; i < 8; i++) m = fmaxf(m, red[i]);
        atomicMax(&g_max[t][b], __float_as_int(m));
    }
}

// ---------------------------------------------------------------------------
// Scatter x2 features into fp32 grid. 32 pts/block, point-major smem,
// one red.global.add.v4.f32 per point per warp (coalesced 512B red).
// ---------------------------------------------------------------------------
__global__ void scatter_kernel(const float* __restrict__ x2f, const float* __restrict__ x2c) {
    int b    = blockIdx.x >> 10;
    int tile = blockIdx.x & 1023;
    int n0   = tile * 32;
    int tx = threadIdx.x, warp = tx >> 5, lane = tx & 31;

    __shared__ float smf[32][132];   // point-major; row stride 132 words
    __shared__ int   ssidx[32];      // voxel*CH element offset

    if (tx < 32) {
        int n = n0 + tx;
        const float* c = x2c + (size_t)b * 3 * NPTS;
        float inv = 0.5f / sqrtf(__int_as_float(g_max[1][b]));
        float mx = g_sum[1][b][0] * (1.0f / NPTS);
        float my = g_sum[1][b][1] * (1.0f / NPTS);
        float mz = g_sum[1][b][2] * (1.0f / NPTS);
        float fx = ((c[n]            - mx) * inv + 0.5f) * (float)RES;
        float fy = ((c[NPTS + n]     - my) * inv + 0.5f) * (float)RES;
        float fz = ((c[2 * NPTS + n] - mz) * inv + 0.5f) * (float)RES;
        int vx = (int)rintf(fminf(fmaxf(fx, 0.f), (float)(RES - 1)));
        int vy = (int)rintf(fminf(fmaxf(fy, 0.f), (float)(RES - 1)));
        int vz = (int)rintf(fminf(fmaxf(fz, 0.f), (float)(RES - 1)));
        int v = (vx * RES + vy) * RES + vz;
        ssidx[tx] = v * CH;
        atomicAdd(&g_cnt[b * R3 + v], 1.0f);
    }
    // coalesced channel-row loads -> point-major smem (4-way write conflict, OK)
    const float* fbase = x2f + (size_t)b * CH * NPTS + n0;
    #pragma unroll
    for (int c = warp; c < CH; c += 8)
        smf[lane][c] = fbase[(size_t)c * NPTS + lane];
    __syncthreads();

    // per point: conflict-free float4 smem read + one vector red (512B coalesced)
    float* gb = g_grid + (size_t)b * R3 * CH;
    #pragma unroll
    for (int i = 0; i < 4; i++) {
        int p = (warp << 2) | i;
        float4 v4 = *(const float4*)&smf[p][4 * lane];
        float* gp = gb + ssidx[p] + 4 * lane;
        asm volatile("red.global.add.v4.f32 [%0], {%1,%2,%3,%4};"
                     :: "l"(gp), "f"(v4.x), "f"(v4.y), "f"(v4.z), "f"(v4.w)
                     : "memory");
    }
}

// ---------------------------------------------------------------------------
// Convert fp32 sums -> fp16 averages (cnt folded in). One thread per 4 channels.
// ---------------------------------------------------------------------------
__global__ void convert_kernel() {
    size_t gid = (size_t)blockIdx.x * 256 + threadIdx.x;   // 8.4M threads
    size_t v = gid >> 5;
    int g = (int)(gid & 31);
    float4 s = *(const float4*)&g_grid[v * CH + 4 * g];
    float inv = 1.0f / fmaxf(g_cnt[v], 1.0f);
    __half2 h0 = __floats2half2_rn(s.x * inv, s.y * inv);
    __half2 h1 = __floats2half2_rn(s.z * inv, s.w * inv);
    uint2 u;
    u.x = *(unsigned*)&h0;
    u.y = *(unsigned*)&h1;
    *(uint2*)&g_gridh[v * CH + 4 * g] = u;
}

// ---------------------------------------------------------------------------
// Trilinear devoxelize from fp16 grid + concat + x1 copy.
// Register-flow gather, conflict-free STS.128/LDS.128 transpose.
// ---------------------------------------------------------------------------
__global__ void devox_kernel(const float* __restrict__ x1f, const float* __restrict__ x1c,
                             float* __restrict__ out) {
    int b    = blockIdx.x >> 10;
    int tile = blockIdx.x & 1023;
    int n0   = tile * 32;
    int tx = threadIdx.x, warp = tx >> 5, lane = tx & 31;

    __shared__ float4 sm4[32][33];   // [point][chGroup], 33-granule pad: conflict-free
    __shared__ int    sidx[32][8];   // voxel*CH
    __shared__ float  sw[32][8];

    // parallel setup: thread (p = tx&31, k = tx>>5) computes corner k of point p
    {
        int p = tx & 31, k = tx >> 5;
        int n = n0 + p;
        const float* c = x1c + (size_t)b * 3 * NPTS;
        float inv = 0.5f / sqrtf(__int_as_float(g_max[0][b]));
        float mx = g_sum[0][b][0] * (1.0f / NPTS);
        float my = g_sum[0][b][1] * (1.0f / NPTS);
        float mz = g_sum[0][b][2] * (1.0f / NPTS);
        float nc0 = fminf(fmaxf(((c[n]            - mx) * inv + 0.5f) * (float)RES, 0.f), (float)(RES - 1));
        float nc1 = fminf(fmaxf(((c[NPTS + n]     - my) * inv + 0.5f) * (float)RES, 0.f), (float)(RES - 1));
        float nc2 = fminf(fmaxf(((c[2 * NPTS + n] - mz) * inv + 0.5f) * (float)RES, 0.f), (float)(RES - 1));
        float f0 = floorf(nc0), f1 = floorf(nc1), f2 = floorf(nc2);
        int lx = (int)f0, ly = (int)f1, lz = (int)f2;
        float dx = nc0 - f0, dy = nc1 - f1, dz = nc2 - f2;
        int hx = min(lx + 1, RES - 1), hy = min(ly + 1, RES - 1), hz = min(lz + 1, RES - 1);
        int xi = (k & 4) ? hx : lx;
        int yi = (k & 2) ? hy : ly;
        int zi = (k & 1) ? hz : lz;
        float wgt = ((k & 4) ? dx : 1.f - dx) *
                    ((k & 2) ? dy : 1.f - dy) *
                    ((k & 1) ? dz : 1.f - dz);
        sidx[p][k] = ((xi * RES + yi) * RES + zi) * CH;
        sw[p][k]   = wgt;
    }
    __syncthreads();

    // gather: warp handles 4 points; lane = channel group (4 contiguous channels)
    const __half* gb = g_gridh + (size_t)b * R3 * CH;
    #pragma unroll
    for (int i = 0; i < 4; i++) {
        int p = (warp << 2) | i;
        float ax = 0.f, ay = 0.f, az = 0.f, aw = 0.f;
        #pragma unroll
        for (int k = 0; k < 8; k++) {
            float wk = sw[p][k];
            uint2 u = *(const uint2*)(gb + sidx[p][k] + 4 * lane);
            __half2 h0 = *(__half2*)&u.x;
            __half2 h1 = *(__half2*)&u.y;
            float2 q0 = __half22float2(h0);
            float2 q1 = __half22float2(h1);
            ax = fmaf(wk, q0.x, ax); ay = fmaf(wk, q0.y, ay);
            az = fmaf(wk, q1.x, az); aw = fmaf(wk, q1.y, aw);
        }
        sm4[p][lane] = make_float4(ax, ay, az, aw);   // STS.128 conflict-free
    }
    __syncthreads();

    // out: conflict-free LDS.128 per channel group, 4 coalesced row STGs
    float* ob = out + ((size_t)b * 2 * CH + CH) * NPTS + n0;
    #pragma unroll
    for (int g = warp; g < 32; g += 8) {
        float4 f = sm4[lane][g];                      // LDS.128 conflict-free
        ob[(size_t)(4 * g + 0) * NPTS + lane] = f.x;
        ob[(size_t)(4 * g + 1) * NPTS + lane] = f.y;
        ob[(size_t)(4 * g + 2) * NPTS + lane] = f.z;
        ob[(size_t)(4 * g + 3) * NPTS + lane] = f.w;
    }
    // x1 passthrough copy (coalesced rows)
    const float* xb = x1f + (size_t)b * CH * NPTS + n0;
    float* ob2 = out + (size_t)b * 2 * CH * NPTS + n0;
    #pragma unroll
    for (int c = warp; c < CH; c += 8)
        ob2[(size_t)c * NPTS + lane] = xb[(size_t)c * NPTS + lane];
}

// ---------------------------------------------------------------------------
extern "C" void kernel_launch(void* const* d_in, const int* in_sizes, int n_in,
                              void* d_out, int out_size) {
    const float* x1f = (const float*)d_in[0];
    const float* x2f = (const float*)d_in[1];
    const float* x1c = (const float*)d_in[2];
    const float* x2c = (const float*)d_in[3];
    float* out = (float*)d_out;

    zero_kernel<<<4096, 256>>>();
    mean_kernel<<<128, 256>>>(x1c, x2c);
    max_kernel<<<128, 256>>>(x1c, x2c);
    scatter_kernel<<<BATCH * (NPTS / 32), 256>>>(x2f, x2c);
    convert_kernel<<<(BATCH * R3 * CH / 4) / 256, 256>>>();
    devox_kernel<<<BATCH * (NPTS / 32), 256>>>(x1f, x1c, out);
}

// round 5
// speedup vs baseline: 1.5050x; 1.0860x over previous
#include <cuda_runtime.h>
#include <cuda_fp16.h>

#define NPTS  32768
#define BATCH 8
#define CH    128
#define RES   32
#define R3    32768   // 32^3

// Scratch (device globals: no allocation allowed)
__device__ __half g_gridh[(size_t)BATCH * R3 * CH];   // fp16 scatter sums [b][v][c] (64 MB, L2-resident)
__device__ float  g_cnt  [BATCH * R3];
__device__ float  g_sum  [2][BATCH][3];               // mean partials (atomicAdd)
__device__ int    g_max  [2][BATCH];                  // max ||c-mean||^2 as int bits

// ---------------------------------------------------------------------------
// Zero fp16 grid + counts + stat accumulators (graph replays -> every launch)
// ---------------------------------------------------------------------------
__global__ void zero_kernel() {
    const size_t gtotal = (size_t)BATCH * R3 * CH * 2 / 16;   // 4M float4
    float4* p = (float4*)g_gridh;
    size_t stride = (size_t)gridDim.x * blockDim.x;
    for (size_t i = (size_t)blockIdx.x * blockDim.x + threadIdx.x; i < gtotal; i += stride)
        p[i] = make_float4(0.f, 0.f, 0.f, 0.f);
    const size_t ctotal = (size_t)BATCH * R3 / 4;
    float4* q = (float4*)g_cnt;
    for (size_t i = (size_t)blockIdx.x * blockDim.x + threadIdx.x; i < ctotal; i += stride)
        q[i] = make_float4(0.f, 0.f, 0.f, 0.f);
    if (blockIdx.x == 0 && threadIdx.x < 64) {
        if (threadIdx.x < 48) ((float*)g_sum)[threadIdx.x] = 0.f;
        else                  ((int*)g_max)[threadIdx.x - 48] = 0;
    }
}

// ---------------------------------------------------------------------------
// Mean partials: 128 blocks (2 tensors x 8 batches x 8 chunks)
// ---------------------------------------------------------------------------
__global__ void mean_kernel(const float* __restrict__ c1, const float* __restrict__ c2) {
    int id = blockIdx.x;
    int t = id >> 6, b = (id >> 3) & 7, s = id & 7;
    const float* c = (t ? c2 : c1) + (size_t)b * 3 * NPTS + s * 4096;

    float s0 = 0.f, s1 = 0.f, s2 = 0.f;
    for (int n = threadIdx.x; n < 4096; n += 256) {
        s0 += c[n]; s1 += c[NPTS + n]; s2 += c[2 * NPTS + n];
    }
    #pragma unroll
    for (int off = 16; off; off >>= 1) {
        s0 += __shfl_down_sync(0xffffffffu, s0, off);
        s1 += __shfl_down_sync(0xffffffffu, s1, off);
        s2 += __shfl_down_sync(0xffffffffu, s2, off);
    }
    __shared__ float red[3][8];
    int lane = threadIdx.x & 31, w = threadIdx.x >> 5;
    if (lane == 0) { red[0][w] = s0; red[1][w] = s1; red[2][w] = s2; }
    __syncthreads();
    if (threadIdx.x == 0) {
        float m0 = 0.f, m1 = 0.f, m2 = 0.f;
        #pragma unroll
        for (int i = 0; i < 8; i++) { m0 += red[0][i]; m1 += red[1][i]; m2 += red[2][i]; }
        atomicAdd(&g_sum[t][b][0], m0);
        atomicAdd(&g_sum[t][b][1], m1);
        atomicAdd(&g_sum[t][b][2], m2);
    }
}

// ---------------------------------------------------------------------------
// Max ||c - mean||^2 partials (int-bit atomicMax, values >= 0)
// ---------------------------------------------------------------------------
__global__ void max_kernel(const float* __restrict__ c1, const float* __restrict__ c2) {
    int id = blockIdx.x;
    int t = id >> 6, b = (id >> 3) & 7, s = id & 7;
    const float* c = (t ? c2 : c1) + (size_t)b * 3 * NPTS + s * 4096;
    float mx = g_sum[t][b][0] * (1.0f / NPTS);
    float my = g_sum[t][b][1] * (1.0f / NPTS);
    float mz = g_sum[t][b][2] * (1.0f / NPTS);

    float best = 0.f;
    for (int n = threadIdx.x; n < 4096; n += 256) {
        float x = c[n] - mx, y = c[NPTS + n] - my, z = c[2 * NPTS + n] - mz;
        best = fmaxf(best, x * x + y * y + z * z);
    }
    #pragma unroll
    for (int off = 16; off; off >>= 1)
        best = fmaxf(best, __shfl_down_sync(0xffffffffu, best, off));
    __shared__ float red[8];
    int lane = threadIdx.x & 31, w = threadIdx.x >> 5;
    if (lane == 0) red[w] = best;
    __syncthreads();
    if (threadIdx.x == 0) {
        float m = 0.f;
        #pragma unroll
        for (int i = 0; i < 8; i++) m = fmaxf(m, red[i]);
        atomicMax(&g_max[t][b], __float_as_int(m));
    }
}

// ---------------------------------------------------------------------------
// Scatter x2 features DIRECTLY into fp16 grid via red.global.add.noftz.v2.f16x2.
// 32 pts/block; one 8B vector red per lane per point (L2-resident target).
// ---------------------------------------------------------------------------
__global__ void scatter_kernel(const float* __restrict__ x2f, const float* __restrict__ x2c) {
    int b    = blockIdx.x >> 10;
    int tile = blockIdx.x & 1023;
    int n0   = tile * 32;
    int tx = threadIdx.x, warp = tx >> 5, lane = tx & 31;

    __shared__ float smf[32][132];   // point-major; row stride 132 words
    __shared__ int   ssidx[32];      // voxel*CH element offset

    if (tx < 32) {
        int n = n0 + tx;
        const float* c = x2c + (size_t)b * 3 * NPTS;
        float inv = 0.5f / sqrtf(__int_as_float(g_max[1][b]));
        float mx = g_sum[1][b][0] * (1.0f / NPTS);
        float my = g_sum[1][b][1] * (1.0f / NPTS);
        float mz = g_sum[1][b][2] * (1.0f / NPTS);
        float fx = ((c[n]            - mx) * inv + 0.5f) * (float)RES;
        float fy = ((c[NPTS + n]     - my) * inv + 0.5f) * (float)RES;
        float fz = ((c[2 * NPTS + n] - mz) * inv + 0.5f) * (float)RES;
        int vx = (int)rintf(fminf(fmaxf(fx, 0.f), (float)(RES - 1)));
        int vy = (int)rintf(fminf(fmaxf(fy, 0.f), (float)(RES - 1)));
        int vz = (int)rintf(fminf(fmaxf(fz, 0.f), (float)(RES - 1)));
        int v = (vx * RES + vy) * RES + vz;
        ssidx[tx] = v * CH;
        atomicAdd(&g_cnt[b * R3 + v], 1.0f);
    }
    // coalesced channel-row loads (streaming hint) -> point-major smem
    const float* fbase = x2f + (size_t)b * CH * NPTS + n0;
    #pragma unroll
    for (int c = warp; c < CH; c += 8)
        smf[lane][c] = __ldcs(&fbase[(size_t)c * NPTS + lane]);
    __syncthreads();

    // per point: conflict-free float4 smem read -> one 8B f16x2 vector red
    __half* gb = g_gridh + (size_t)b * R3 * CH;
    #pragma unroll
    for (int i = 0; i < 4; i++) {
        int p = (warp << 2) | i;
        float4 v4 = *(const float4*)&smf[p][4 * lane];
        __half2 h0 = __floats2half2_rn(v4.x, v4.y);
        __half2 h1 = __floats2half2_rn(v4.z, v4.w);
        __half* gp = gb + ssidx[p] + 4 * lane;
        asm volatile("red.global.add.noftz.v2.f16x2 [%0], {%1, %2};"
                     :: "l"(gp), "r"(*(unsigned*)&h0), "r"(*(unsigned*)&h1)
                     : "memory");
    }
}

// ---------------------------------------------------------------------------
// Trilinear devoxelize from fp16 sum-grid (cnt folded into corner weights)
// + concat + x1 copy. Register-flow gather, conflict-free smem transpose.
// ---------------------------------------------------------------------------
__global__ void devox_kernel(const float* __restrict__ x1f, const float* __restrict__ x1c,
                             float* __restrict__ out) {
    int b    = blockIdx.x >> 10;
    int tile = blockIdx.x & 1023;
    int n0   = tile * 32;
    int tx = threadIdx.x, warp = tx >> 5, lane = tx & 31;

    __shared__ float4 sm4[32][33];   // [point][chGroup], padded: conflict-free
    __shared__ int    sidx[32][8];   // voxel*CH
    __shared__ float  sw[32][8];     // weight / max(cnt,1)

    // parallel setup: thread (p = tx&31, k = tx>>5) computes corner k of point p
    {
        int p = tx & 31, k = tx >> 5;
        int n = n0 + p;
        const float* c = x1c + (size_t)b * 3 * NPTS;
        float inv = 0.5f / sqrtf(__int_as_float(g_max[0][b]));
        float mx = g_sum[0][b][0] * (1.0f / NPTS);
        float my = g_sum[0][b][1] * (1.0f / NPTS);
        float mz = g_sum[0][b][2] * (1.0f / NPTS);
        float nc0 = fminf(fmaxf(((c[n]            - mx) * inv + 0.5f) * (float)RES, 0.f), (float)(RES - 1));
        float nc1 = fminf(fmaxf(((c[NPTS + n]     - my) * inv + 0.5f) * (float)RES, 0.f), (float)(RES - 1));
        float nc2 = fminf(fmaxf(((c[2 * NPTS + n] - mz) * inv + 0.5f) * (float)RES, 0.f), (float)(RES - 1));
        float f0 = floorf(nc0), f1 = floorf(nc1), f2 = floorf(nc2);
        int lx = (int)f0, ly = (int)f1, lz = (int)f2;
        float dx = nc0 - f0, dy = nc1 - f1, dz = nc2 - f2;
        int hx = min(lx + 1, RES - 1), hy = min(ly + 1, RES - 1), hz = min(lz + 1, RES - 1);
        int xi = (k & 4) ? hx : lx;
        int yi = (k & 2) ? hy : ly;
        int zi = (k & 1) ? hz : lz;
        float wgt = ((k & 4) ? dx : 1.f - dx) *
                    ((k & 2) ? dy : 1.f - dy) *
                    ((k & 1) ? dz : 1.f - dz);
        int v = (xi * RES + yi) * RES + zi;
        sidx[p][k] = v * CH;
        sw[p][k]   = wgt / fmaxf(g_cnt[b * R3 + v], 1.0f);
    }
    __syncthreads();

    // gather: warp handles 4 points; lane = channel group (4 contiguous channels)
    const __half* gb = g_gridh + (size_t)b * R3 * CH;
    #pragma unroll
    for (int i = 0; i < 4; i++) {
        int p = (warp << 2) | i;
        float ax = 0.f, ay = 0.f, az = 0.f, aw = 0.f;
        #pragma unroll
        for (int k = 0; k < 8; k++) {
            float wk = sw[p][k];
            uint2 u = *(const uint2*)(gb + sidx[p][k] + 4 * lane);
            float2 q0 = __half22float2(*(__half2*)&u.x);
            float2 q1 = __half22float2(*(__half2*)&u.y);
            ax = fmaf(wk, q0.x, ax); ay = fmaf(wk, q0.y, ay);
            az = fmaf(wk, q1.x, az); aw = fmaf(wk, q1.y, aw);
        }
        sm4[p][lane] = make_float4(ax, ay, az, aw);   // STS.128 conflict-free
    }
    __syncthreads();

    // out: conflict-free LDS.128 per channel group, coalesced streaming STGs
    float* ob = out + ((size_t)b * 2 * CH + CH) * NPTS + n0;
    #pragma unroll
    for (int g = warp; g < 32; g += 8) {
        float4 f = sm4[lane][g];                      // LDS.128 conflict-free
        __stcs(&ob[(size_t)(4 * g + 0) * NPTS + lane], f.x);
        __stcs(&ob[(size_t)(4 * g + 1) * NPTS + lane], f.y);
        __stcs(&ob[(size_t)(4 * g + 2) * NPTS + lane], f.z);
        __stcs(&ob[(size_t)(4 * g + 3) * NPTS + lane], f.w);
    }
    // x1 passthrough copy (coalesced rows, streaming both ways)
    const float* xb = x1f + (size_t)b * CH * NPTS + n0;
    float* ob2 = out + (size_t)b * 2 * CH * NPTS + n0;
    #pragma unroll
    for (int c = warp; c < CH; c += 8)
        __stcs(&ob2[(size_t)c * NPTS + lane], __ldcs(&xb[(size_t)c * NPTS + lane]));
}

// ---------------------------------------------------------------------------
extern "C" void kernel_launch(void* const* d_in, const int* in_sizes, int n_in,
                              void* d_out, int out_size) {
    const float* x1f = (const float*)d_in[0];
    const float* x2f = (const float*)d_in[1];
    const float* x1c = (const float*)d_in[2];
    const float* x2c = (const float*)d_in[3];
    float* out = (float*)d_out;

    zero_kernel<<<4096, 256>>>();
    mean_kernel<<<128, 256>>>(x1c, x2c);
    max_kernel<<<128, 256>>>(x1c, x2c);
    scatter_kernel<<<BATCH * (NPTS / 32), 256>>>(x2f, x2c);
    devox_kernel<<<BATCH * (NPTS / 32), 256>>>(x1f, x1c, out);
}

// round 6
// speedup vs baseline: 1.6281x; 1.0818x over previous
#include <cuda_runtime.h>
#include <cuda_fp16.h>

#define NPTS  32768
#define BATCH 8
#define CH    128
#define RES   32
#define R3    32768   // 32^3

// Scratch (device globals: no allocation allowed)
__device__ __half g_gridh[(size_t)BATCH * R3 * CH];   // fp16 scatter sums [b][v][c] (64 MB, L2-resident)
__device__ float  g_cnt  [BATCH * R3];
__device__ float  g_sum  [2][BATCH][3];               // mean partials (atomicAdd)
__device__ int    g_max  [2][BATCH];                  // max ||c-mean||^2 as int bits

// ---------------------------------------------------------------------------
// Zero fp16 grid + counts + stat accumulators (graph replays -> every launch)
// ---------------------------------------------------------------------------
__global__ void zero_kernel() {
    const size_t gtotal = (size_t)BATCH * R3 * CH * 2 / 16;   // 4M float4
    float4* p = (float4*)g_gridh;
    size_t stride = (size_t)gridDim.x * blockDim.x;
    for (size_t i = (size_t)blockIdx.x * blockDim.x + threadIdx.x; i < gtotal; i += stride)
        p[i] = make_float4(0.f, 0.f, 0.f, 0.f);
    const size_t ctotal = (size_t)BATCH * R3 / 4;
    float4* q = (float4*)g_cnt;
    for (size_t i = (size_t)blockIdx.x * blockDim.x + threadIdx.x; i < ctotal; i += stride)
        q[i] = make_float4(0.f, 0.f, 0.f, 0.f);
    if (blockIdx.x == 0 && threadIdx.x < 64) {
        if (threadIdx.x < 48) ((float*)g_sum)[threadIdx.x] = 0.f;
        else                  ((int*)g_max)[threadIdx.x - 48] = 0;
    }
}

// ---------------------------------------------------------------------------
// Mean partials: 128 blocks (2 tensors x 8 batches x 8 chunks)
// ---------------------------------------------------------------------------
__global__ void mean_kernel(const float* __restrict__ c1, const float* __restrict__ c2) {
    int id = blockIdx.x;
    int t = id >> 6, b = (id >> 3) & 7, s = id & 7;
    const float* c = (t ? c2 : c1) + (size_t)b * 3 * NPTS + s * 4096;

    float s0 = 0.f, s1 = 0.f, s2 = 0.f;
    for (int n = threadIdx.x; n < 4096; n += 256) {
        s0 += c[n]; s1 += c[NPTS + n]; s2 += c[2 * NPTS + n];
    }
    #pragma unroll
    for (int off = 16; off; off >>= 1) {
        s0 += __shfl_down_sync(0xffffffffu, s0, off);
        s1 += __shfl_down_sync(0xffffffffu, s1, off);
        s2 += __shfl_down_sync(0xffffffffu, s2, off);
    }
    __shared__ float red[3][8];
    int lane = threadIdx.x & 31, w = threadIdx.x >> 5;
    if (lane == 0) { red[0][w] = s0; red[1][w] = s1; red[2][w] = s2; }
    __syncthreads();
    if (threadIdx.x == 0) {
        float m0 = 0.f, m1 = 0.f, m2 = 0.f;
        #pragma unroll
        for (int i = 0; i < 8; i++) { m0 += red[0][i]; m1 += red[1][i]; m2 += red[2][i]; }
        atomicAdd(&g_sum[t][b][0], m0);
        atomicAdd(&g_sum[t][b][1], m1);
        atomicAdd(&g_sum[t][b][2], m2);
    }
}

// ---------------------------------------------------------------------------
// Max ||c - mean||^2 partials (int-bit atomicMax, values >= 0)
// ---------------------------------------------------------------------------
__global__ void max_kernel(const float* __restrict__ c1, const float* __restrict__ c2) {
    int id = blockIdx.x;
    int t = id >> 6, b = (id >> 3) & 7, s = id & 7;
    const float* c = (t ? c2 : c1) + (size_t)b * 3 * NPTS + s * 4096;
    float mx = g_sum[t][b][0] * (1.0f / NPTS);
    float my = g_sum[t][b][1] * (1.0f / NPTS);
    float mz = g_sum[t][b][2] * (1.0f / NPTS);

    float best = 0.f;
    for (int n = threadIdx.x; n < 4096; n += 256) {
        float x = c[n] - mx, y = c[NPTS + n] - my, z = c[2 * NPTS + n] - mz;
        best = fmaxf(best, x * x + y * y + z * z);
    }
    #pragma unroll
    for (int off = 16; off; off >>= 1)
        best = fmaxf(best, __shfl_down_sync(0xffffffffu, best, off));
    __shared__ float red[8];
    int lane = threadIdx.x & 31, w = threadIdx.x >> 5;
    if (lane == 0) red[w] = best;
    __syncthreads();
    if (threadIdx.x == 0) {
        float m = 0.f;
        #pragma unroll
        for (int i = 0; i < 8; i++) m = fmaxf(m, red[i]);
        atomicMax(&g_max[t][b], __float_as_int(m));
    }
}

// ---------------------------------------------------------------------------
// Scatter x2 -> fp16 grid (128-bit v4.f16x2 reds) FUSED with the independent
// x1 -> out passthrough copy (fills idle DRAM bandwidth in this phase).
// ---------------------------------------------------------------------------
__global__ void scatter_copy_kernel(const float* __restrict__ x2f, const float* __restrict__ x2c,
                                    const float* __restrict__ x1f, float* __restrict__ out) {
    int b    = blockIdx.x >> 10;
    int tile = blockIdx.x & 1023;
    int n0   = tile * 32;
    int tx = threadIdx.x, warp = tx >> 5, lane = tx & 31;

    __shared__ float smf[32][132];   // point-major; row stride 132 words (16B-multiple)
    __shared__ int   ssidx[32];      // voxel*CH element offset

    if (tx < 32) {
        int n = n0 + tx;
        const float* c = x2c + (size_t)b * 3 * NPTS;
        float inv = 0.5f / sqrtf(__int_as_float(g_max[1][b]));
        float mx = g_sum[1][b][0] * (1.0f / NPTS);
        float my = g_sum[1][b][1] * (1.0f / NPTS);
        float mz = g_sum[1][b][2] * (1.0f / NPTS);
        float fx = ((c[n]            - mx) * inv + 0.5f) * (float)RES;
        float fy = ((c[NPTS + n]     - my) * inv + 0.5f) * (float)RES;
        float fz = ((c[2 * NPTS + n] - mz) * inv + 0.5f) * (float)RES;
        int vx = (int)rintf(fminf(fmaxf(fx, 0.f), (float)(RES - 1)));
        int vy = (int)rintf(fminf(fmaxf(fy, 0.f), (float)(RES - 1)));
        int vz = (int)rintf(fminf(fmaxf(fz, 0.f), (float)(RES - 1)));
        int v = (vx * RES + vy) * RES + vz;
        ssidx[tx] = v * CH;
        atomicAdd(&g_cnt[b * R3 + v], 1.0f);
    }
    // coalesced channel-row loads (streaming hint) -> point-major smem
    const float* fbase = x2f + (size_t)b * CH * NPTS + n0;
    #pragma unroll
    for (int c = warp; c < CH; c += 8)
        smf[lane][c] = __ldcs(&fbase[(size_t)c * NPTS + lane]);
    __syncthreads();

    // per point: half-warp (16 lanes x 8ch) -> one 16B v4.f16x2 vector red
    __half* gb = g_gridh + (size_t)b * R3 * CH;
    #pragma unroll
    for (int i = 0; i < 2; i++) {
        int p = (warp << 2) | (i << 1) | (lane >> 4);   // 2 points per pass
        int g = lane & 15;                               // 8-channel group
        float4 va = *(const float4*)&smf[p][8 * g];
        float4 vb = *(const float4*)&smf[p][8 * g + 4];
        __half2 h0 = __floats2half2_rn(va.x, va.y);
        __half2 h1 = __floats2half2_rn(va.z, va.w);
        __half2 h2 = __floats2half2_rn(vb.x, vb.y);
        __half2 h3 = __floats2half2_rn(vb.z, vb.w);
        __half* gp = gb + ssidx[p] + 8 * g;
        asm volatile("red.global.add.noftz.v4.f16x2 [%0], {%1, %2, %3, %4};"
                     :: "l"(gp), "r"(*(unsigned*)&h0), "r"(*(unsigned*)&h1),
                        "r"(*(unsigned*)&h2), "r"(*(unsigned*)&h3)
                     : "memory");
    }

    // fused independent x1 passthrough copy (coalesced rows, streaming)
    const float* xb = x1f + (size_t)b * CH * NPTS + n0;
    float* ob = out + (size_t)b * 2 * CH * NPTS + n0;
    #pragma unroll
    for (int c = warp; c < CH; c += 8)
        __stcs(&ob[(size_t)c * NPTS + lane], __ldcs(&xb[(size_t)c * NPTS + lane]));
}

// ---------------------------------------------------------------------------
// Trilinear devoxelize from fp16 sum-grid (cnt folded into corner weights).
// uint4 gathers (8 ch/lane, half-warp per point), writes out second half only.
// ---------------------------------------------------------------------------
__global__ void devox_kernel(const float* __restrict__ x1c, float* __restrict__ out) {
    int b    = blockIdx.x >> 10;
    int tile = blockIdx.x & 1023;
    int n0   = tile * 32;
    int tx = threadIdx.x, warp = tx >> 5, lane = tx & 31;

    __shared__ float4 sm4[32][33];   // [point][col]; lane g stores cols g and 16+g
    __shared__ int    sidx[32][8];   // voxel*CH
    __shared__ float  sw[32][8];     // weight / max(cnt,1)

    // parallel setup: thread (p = tx&31, k = tx>>5) computes corner k of point p
    {
        int p = tx & 31, k = tx >> 5;
        int n = n0 + p;
        const float* c = x1c + (size_t)b * 3 * NPTS;
        float inv = 0.5f / sqrtf(__int_as_float(g_max[0][b]));
        float mx = g_sum[0][b][0] * (1.0f / NPTS);
        float my = g_sum[0][b][1] * (1.0f / NPTS);
        float mz = g_sum[0][b][2] * (1.0f / NPTS);
        float nc0 = fminf(fmaxf(((c[n]            - mx) * inv + 0.5f) * (float)RES, 0.f), (float)(RES - 1));
        float nc1 = fminf(fmaxf(((c[NPTS + n]     - my) * inv + 0.5f) * (float)RES, 0.f), (float)(RES - 1));
        float nc2 = fminf(fmaxf(((c[2 * NPTS + n] - mz) * inv + 0.5f) * (float)RES, 0.f), (float)(RES - 1));
        float f0 = floorf(nc0), f1 = floorf(nc1), f2 = floorf(nc2);
        int lx = (int)f0, ly = (int)f1, lz = (int)f2;
        float dx = nc0 - f0, dy = nc1 - f1, dz = nc2 - f2;
        int hx = min(lx + 1, RES - 1), hy = min(ly + 1, RES - 1), hz = min(lz + 1, RES - 1);
        int xi = (k & 4) ? hx : lx;
        int yi = (k & 2) ? hy : ly;
        int zi = (k & 1) ? hz : lz;
        float wgt = ((k & 4) ? dx : 1.f - dx) *
                    ((k & 2) ? dy : 1.f - dy) *
                    ((k & 1) ? dz : 1.f - dz);
        int v = (xi * RES + yi) * RES + zi;
        sidx[p][k] = v * CH;
        sw[p][k]   = wgt / fmaxf(g_cnt[b * R3 + v], 1.0f);
    }
    __syncthreads();

    // gather: half-warp per point, lane covers 8 consecutive channels (LDG.128)
    const __half* gb = g_gridh + (size_t)b * R3 * CH;
    #pragma unroll
    for (int i = 0; i < 2; i++) {
        int p = (warp << 2) | (i << 1) | (lane >> 4);
        int g = lane & 15;
        float a0 = 0.f, a1 = 0.f, a2 = 0.f, a3 = 0.f;
        float a4 = 0.f, a5 = 0.f, a6 = 0.f, a7 = 0.f;
        #pragma unroll
        for (int k = 0; k < 8; k++) {
            float wk = sw[p][k];
            uint4 u = *(const uint4*)(gb + sidx[p][k] + 8 * g);
            float2 q0 = __half22float2(*(__half2*)&u.x);
            float2 q1 = __half22float2(*(__half2*)&u.y);
            float2 q2 = __half22float2(*(__half2*)&u.z);
            float2 q3 = __half22float2(*(__half2*)&u.w);
            a0 = fmaf(wk, q0.x, a0); a1 = fmaf(wk, q0.y, a1);
            a2 = fmaf(wk, q1.x, a2); a3 = fmaf(wk, q1.y, a3);
            a4 = fmaf(wk, q2.x, a4); a5 = fmaf(wk, q2.y, a5);
            a6 = fmaf(wk, q3.x, a6); a7 = fmaf(wk, q3.y, a7);
        }
        // cols g (ch 8g..8g+3) and 16+g (ch 8g+4..8g+7): both STS.128 conflict-free
        sm4[p][g]      = make_float4(a0, a1, a2, a3);
        sm4[p][16 + g] = make_float4(a4, a5, a6, a7);
    }
    __syncthreads();

    // out: conflict-free LDS.128 per column, coalesced streaming STGs
    float* ob = out + ((size_t)b * 2 * CH + CH) * NPTS + n0;
    #pragma unroll
    for (int g2 = warp; g2 < 32; g2 += 8) {
        float4 f = sm4[lane][g2];                     // LDS.128 conflict-free
        int ch0 = (g2 < 16) ? 8 * g2 : 8 * (g2 - 16) + 4;
        __stcs(&ob[(size_t)(ch0 + 0) * NPTS + lane], f.x);
        __stcs(&ob[(size_t)(ch0 + 1) * NPTS + lane], f.y);
        __stcs(&ob[(size_t)(ch0 + 2) * NPTS + lane], f.z);
        __stcs(&ob[(size_t)(ch0 + 3) * NPTS + lane], f.w);
    }
}

// ---------------------------------------------------------------------------
extern "C" void kernel_launch(void* const* d_in, const int* in_sizes, int n_in,
                              void* d_out, int out_size) {
    const float* x1f = (const float*)d_in[0];
    const float* x2f = (const float*)d_in[1];
    const float* x1c = (const float*)d_in[2];
    const float* x2c = (const float*)d_in[3];
    float* out = (float*)d_out;

    zero_kernel<<<4096, 256>>>();
    mean_kernel<<<128, 256>>>(x1c, x2c);
    max_kernel<<<128, 256>>>(x1c, x2c);
    scatter_copy_kernel<<<BATCH * (NPTS / 32), 256>>>(x2f, x2c, x1f, out);
    devox_kernel<<<BATCH * (NPTS / 32), 256>>>(x1c, out);
}

// round 7
// speedup vs baseline: 1.8118x; 1.1128x over previous
#include <cuda_runtime.h>
#include <cuda_fp16.h>

#define NPTS  32768
#define BATCH 8
#define CH    128
#define RES   32
#define R3    32768   // 32^3

// Scratch (device globals: no allocation allowed)
__device__ __half g_gridh[(size_t)BATCH * R3 * CH];   // fp16 scatter sums [b][v][c] (64 MB)
__device__ float  g_cnt  [BATCH * R3];
__device__ float  g_sum  [2][BATCH][3];               // mean partials (atomicAdd)
__device__ int    g_max  [2][BATCH];                  // max ||c-mean||^2 as int bits

// ---------------------------------------------------------------------------
// Zero fp16 grid + counts + stat accumulators (graph replays -> every launch)
// ---------------------------------------------------------------------------
__global__ void zero_kernel() {
    const size_t gtotal = (size_t)BATCH * R3 * CH * 2 / 16;   // 4M float4
    float4* p = (float4*)g_gridh;
    size_t stride = (size_t)gridDim.x * blockDim.x;
    for (size_t i = (size_t)blockIdx.x * blockDim.x + threadIdx.x; i < gtotal; i += stride)
        p[i] = make_float4(0.f, 0.f, 0.f, 0.f);
    const size_t ctotal = (size_t)BATCH * R3 / 4;
    float4* q = (float4*)g_cnt;
    for (size_t i = (size_t)blockIdx.x * blockDim.x + threadIdx.x; i < ctotal; i += stride)
        q[i] = make_float4(0.f, 0.f, 0.f, 0.f);
    if (blockIdx.x == 0 && threadIdx.x < 64) {
        if (threadIdx.x < 48) ((float*)g_sum)[threadIdx.x] = 0.f;
        else                  ((int*)g_max)[threadIdx.x - 48] = 0;
    }
}

// ---------------------------------------------------------------------------
// Mean partials: 128 blocks (2 tensors x 8 batches x 8 chunks)
// ---------------------------------------------------------------------------
__global__ void mean_kernel(const float* __restrict__ c1, const float* __restrict__ c2) {
    int id = blockIdx.x;
    int t = id >> 6, b = (id >> 3) & 7, s = id & 7;
    const float* c = (t ? c2 : c1) + (size_t)b * 3 * NPTS + s * 4096;

    float s0 = 0.f, s1 = 0.f, s2 = 0.f;
    for (int n = threadIdx.x; n < 4096; n += 256) {
        s0 += c[n]; s1 += c[NPTS + n]; s2 += c[2 * NPTS + n];
    }
    #pragma unroll
    for (int off = 16; off; off >>= 1) {
        s0 += __shfl_down_sync(0xffffffffu, s0, off);
        s1 += __shfl_down_sync(0xffffffffu, s1, off);
        s2 += __shfl_down_sync(0xffffffffu, s2, off);
    }
    __shared__ float red[3][8];
    int lane = threadIdx.x & 31, w = threadIdx.x >> 5;
    if (lane == 0) { red[0][w] = s0; red[1][w] = s1; red[2][w] = s2; }
    __syncthreads();
    if (threadIdx.x == 0) {
        float m0 = 0.f, m1 = 0.f, m2 = 0.f;
        #pragma unroll
        for (int i = 0; i < 8; i++) { m0 += red[0][i]; m1 += red[1][i]; m2 += red[2][i]; }
        atomicAdd(&g_sum[t][b][0], m0);
        atomicAdd(&g_sum[t][b][1], m1);
        atomicAdd(&g_sum[t][b][2], m2);
    }
}

// ---------------------------------------------------------------------------
// Max ||c - mean||^2 partials (int-bit atomicMax, values >= 0)
// ---------------------------------------------------------------------------
__global__ void max_kernel(const float* __restrict__ c1, const float* __restrict__ c2) {
    int id = blockIdx.x;
    int t = id >> 6, b = (id >> 3) & 7, s = id & 7;
    const float* c = (t ? c2 : c1) + (size_t)b * 3 * NPTS + s * 4096;
    float mx = g_sum[t][b][0] * (1.0f / NPTS);
    float my = g_sum[t][b][1] * (1.0f / NPTS);
    float mz = g_sum[t][b][2] * (1.0f / NPTS);

    float best = 0.f;
    for (int n = threadIdx.x; n < 4096; n += 256) {
        float x = c[n] - mx, y = c[NPTS + n] - my, z = c[2 * NPTS + n] - mz;
        best = fmaxf(best, x * x + y * y + z * z);
    }
    #pragma unroll
    for (int off = 16; off; off >>= 1)
        best = fmaxf(best, __shfl_down_sync(0xffffffffu, best, off));
    __shared__ float red[8];
    int lane = threadIdx.x & 31, w = threadIdx.x >> 5;
    if (lane == 0) red[w] = best;
    __syncthreads();
    if (threadIdx.x == 0) {
        float m = 0.f;
        #pragma unroll
        for (int i = 0; i < 8; i++) m = fmaxf(m, red[i]);
        atomicMax(&g_max[t][b], __float_as_int(m));
    }
}

// ---------------------------------------------------------------------------
// Scatter x2 -> fp16 grid. Vectorized transpose loads (LDG.128: lane = 4
// consecutive points of one channel), 16B v4.f16x2 reds.
// ---------------------------------------------------------------------------
__global__ void scatter_kernel(const float* __restrict__ x2f, const float* __restrict__ x2c) {
    int b    = blockIdx.x >> 10;
    int tile = blockIdx.x & 1023;
    int n0   = tile * 32;
    int tx = threadIdx.x, warp = tx >> 5, lane = tx & 31;

    __shared__ float smf[32][132];   // point-major; row stride 132 words (16B-multiple)
    __shared__ int   ssidx[32];      // voxel*CH element offset

    if (tx < 32) {
        int n = n0 + tx;
        const float* c = x2c + (size_t)b * 3 * NPTS;
        float inv = 0.5f / sqrtf(__int_as_float(g_max[1][b]));
        float mx = g_sum[1][b][0] * (1.0f / NPTS);
        float my = g_sum[1][b][1] * (1.0f / NPTS);
        float mz = g_sum[1][b][2] * (1.0f / NPTS);
        float fx = ((c[n]            - mx) * inv + 0.5f) * (float)RES;
        float fy = ((c[NPTS + n]     - my) * inv + 0.5f) * (float)RES;
        float fz = ((c[2 * NPTS + n] - mz) * inv + 0.5f) * (float)RES;
        int vx = (int)rintf(fminf(fmaxf(fx, 0.f), (float)(RES - 1)));
        int vy = (int)rintf(fminf(fmaxf(fy, 0.f), (float)(RES - 1)));
        int vz = (int)rintf(fminf(fmaxf(fz, 0.f), (float)(RES - 1)));
        int v = (vx * RES + vy) * RES + vz;
        ssidx[tx] = v * CH;
        atomicAdd(&g_cnt[b * R3 + v], 1.0f);
    }
    // vectorized transpose load: lane covers 4 consecutive points of channel c
    const float4* fb4 = (const float4*)(x2f + (size_t)b * CH * NPTS + n0);
    #pragma unroll
    for (int j = 0; j < 4; j++) {
        int c  = j * 32 + (warp << 2) + (lane >> 3);
        int p4 = lane & 7;
        float4 v = __ldcs(&fb4[(size_t)c * (NPTS / 4) + p4]);
        smf[4 * p4 + 0][c] = v.x;
        smf[4 * p4 + 1][c] = v.y;
        smf[4 * p4 + 2][c] = v.z;
        smf[4 * p4 + 3][c] = v.w;
    }
    __syncthreads();

    // per point: half-warp (16 lanes x 8ch) -> one 16B v4.f16x2 vector red
    __half* gb = g_gridh + (size_t)b * R3 * CH;
    #pragma unroll
    for (int i = 0; i < 2; i++) {
        int p = (warp << 2) | (i << 1) | (lane >> 4);   // 2 points per pass
        int g = lane & 15;                               // 8-channel group
        float4 va = *(const float4*)&smf[p][8 * g];
        float4 vb = *(const float4*)&smf[p][8 * g + 4];
        __half2 h0 = __floats2half2_rn(va.x, va.y);
        __half2 h1 = __floats2half2_rn(va.z, va.w);
        __half2 h2 = __floats2half2_rn(vb.x, vb.y);
        __half2 h3 = __floats2half2_rn(vb.z, vb.w);
        __half* gp = gb + ssidx[p] + 8 * g;
        asm volatile("red.global.add.noftz.v4.f16x2 [%0], {%1, %2, %3, %4};"
                     :: "l"(gp), "r"(*(unsigned*)&h0), "r"(*(unsigned*)&h1),
                        "r"(*(unsigned*)&h2), "r"(*(unsigned*)&h3)
                     : "memory");
    }
}

// ---------------------------------------------------------------------------
// Trilinear devoxelize from fp16 sum-grid (cnt folded into corner weights)
// + flat float4 x1 passthrough copy tail (fills DRAM idle during gathers).
// ---------------------------------------------------------------------------
__global__ void devox_copy_kernel(const float* __restrict__ x1f, const float* __restrict__ x1c,
                                  float* __restrict__ out) {
    int b    = blockIdx.x >> 10;
    int tile = blockIdx.x & 1023;
    int n0   = tile * 32;
    int tx = threadIdx.x, warp = tx >> 5, lane = tx & 31;

    __shared__ float4 sm4[32][33];   // [point][col]; lane g stores cols g and 16+g
    __shared__ int    sidx[32][8];   // voxel*CH
    __shared__ float  sw[32][8];     // weight / max(cnt,1)

    // parallel setup: thread (p = tx&31, k = tx>>5) computes corner k of point p
    {
        int p = tx & 31, k = tx >> 5;
        int n = n0 + p;
        const float* c = x1c + (size_t)b * 3 * NPTS;
        float inv = 0.5f / sqrtf(__int_as_float(g_max[0][b]));
        float mx = g_sum[0][b][0] * (1.0f / NPTS);
        float my = g_sum[0][b][1] * (1.0f / NPTS);
        float mz = g_sum[0][b][2] * (1.0f / NPTS);
        float nc0 = fminf(fmaxf(((c[n]            - mx) * inv + 0.5f) * (float)RES, 0.f), (float)(RES - 1));
        float nc1 = fminf(fmaxf(((c[NPTS + n]     - my) * inv + 0.5f) * (float)RES, 0.f), (float)(RES - 1));
        float nc2 = fminf(fmaxf(((c[2 * NPTS + n] - mz) * inv + 0.5f) * (float)RES, 0.f), (float)(RES - 1));
        float f0 = floorf(nc0), f1 = floorf(nc1), f2 = floorf(nc2);
        int lx = (int)f0, ly = (int)f1, lz = (int)f2;
        float dx = nc0 - f0, dy = nc1 - f1, dz = nc2 - f2;
        int hx = min(lx + 1, RES - 1), hy = min(ly + 1, RES - 1), hz = min(lz + 1, RES - 1);
        int xi = (k & 4) ? hx : lx;
        int yi = (k & 2) ? hy : ly;
        int zi = (k & 1) ? hz : lz;
        float wgt = ((k & 4) ? dx : 1.f - dx) *
                    ((k & 2) ? dy : 1.f - dy) *
                    ((k & 1) ? dz : 1.f - dz);
        int v = (xi * RES + yi) * RES + zi;
        sidx[p][k] = v * CH;
        sw[p][k]   = wgt / fmaxf(g_cnt[b * R3 + v], 1.0f);
    }
    __syncthreads();

    // gather: half-warp per point, lane covers 8 consecutive channels (LDG.128)
    const __half* gb = g_gridh + (size_t)b * R3 * CH;
    #pragma unroll
    for (int i = 0; i < 2; i++) {
        int p = (warp << 2) | (i << 1) | (lane >> 4);
        int g = lane & 15;
        float a0 = 0.f, a1 = 0.f, a2 = 0.f, a3 = 0.f;
        float a4 = 0.f, a5 = 0.f, a6 = 0.f, a7 = 0.f;
        #pragma unroll
        for (int k = 0; k < 8; k++) {
            float wk = sw[p][k];
            uint4 u = *(const uint4*)(gb + sidx[p][k] + 8 * g);
            float2 q0 = __half22float2(*(__half2*)&u.x);
            float2 q1 = __half22float2(*(__half2*)&u.y);
            float2 q2 = __half22float2(*(__half2*)&u.z);
            float2 q3 = __half22float2(*(__half2*)&u.w);
            a0 = fmaf(wk, q0.x, a0); a1 = fmaf(wk, q0.y, a1);
            a2 = fmaf(wk, q1.x, a2); a3 = fmaf(wk, q1.y, a3);
            a4 = fmaf(wk, q2.x, a4); a5 = fmaf(wk, q2.y, a5);
            a6 = fmaf(wk, q3.x, a6); a7 = fmaf(wk, q3.y, a7);
        }
        sm4[p][g]      = make_float4(a0, a1, a2, a3);
        sm4[p][16 + g] = make_float4(a4, a5, a6, a7);
    }
    __syncthreads();

    // out: conflict-free LDS.128 per column, coalesced streaming STGs
    float* ob = out + ((size_t)b * 2 * CH + CH) * NPTS + n0;
    #pragma unroll
    for (int g2 = warp; g2 < 32; g2 += 8) {
        float4 f = sm4[lane][g2];                     // LDS.128 conflict-free
        int ch0 = (g2 < 16) ? 8 * g2 : 8 * (g2 - 16) + 4;
        __stcs(&ob[(size_t)(ch0 + 0) * NPTS + lane], f.x);
        __stcs(&ob[(size_t)(ch0 + 1) * NPTS + lane], f.y);
        __stcs(&ob[(size_t)(ch0 + 2) * NPTS + lane], f.z);
        __stcs(&ob[(size_t)(ch0 + 3) * NPTS + lane], f.w);
    }

    // flat vectorized x1 passthrough copy: out[b][0:128][n] = x1f[b][:][n]
    // element offset e in x1f maps to out offset e + (b<<22), b = e>>22.
    {
        const float4* src = (const float4*)x1f;
        const size_t nvec = (size_t)BATCH * CH * NPTS / 4;   // 16M float4
        size_t stride = (size_t)gridDim.x * blockDim.x;
        for (size_t i = (size_t)blockIdx.x * blockDim.x + tx; i < nvec; i += stride) {
            size_t e = i * 4;
            size_t bb = e >> 22;                              // CH*NPTS = 2^22
            float4 v = __ldcs(&src[i]);
            __stcs((float4*)(out + e + (bb << 22)), v);
        }
    }
}

// ---------------------------------------------------------------------------
extern "C" void kernel_launch(void* const* d_in, const int* in_sizes, int n_in,
                              void* d_out, int out_size) {
    const float* x1f = (const float*)d_in[0];
    const float* x2f = (const float*)d_in[1];
    const float* x1c = (const float*)d_in[2];
    const float* x2c = (const float*)d_in[3];
    float* out = (float*)d_out;

    zero_kernel<<<4096, 256>>>();
    mean_kernel<<<128, 256>>>(x1c, x2c);
    max_kernel<<<128, 256>>>(x1c, x2c);
    scatter_kernel<<<BATCH * (NPTS / 32), 256>>>(x2f, x2c);
    devox_copy_kernel<<<BATCH * (NPTS / 32), 256>>>(x1f, x1c, out);
}